// round 1
// baseline (speedup 1.0000x reference)
#include <cuda_runtime.h>
#include <cstdint>
#include <cstddef>

// Problem constants
#define NTOK 8192
#define IN_DIM 1024
#define HID_DIM 4096
#define OUT_DIM 1024
#define NE 8

// Scratch: h [E][B][HID] (1 GB), y [E][B][OUT] (256 MB)
__device__ float g_h[(size_t)NE * NTOK * HID_DIM];
__device__ float g_y[(size_t)NE * NTOK * OUT_DIM];

__device__ __forceinline__ unsigned f2tf(float x) {
    unsigned r;
    asm("cvt.rna.tf32.f32 %0, %1;" : "=r"(r) : "f"(x));
    return r;
}

__device__ __forceinline__ float geluf(float x) {
    // exact gelu: x * Phi(x)
    return 0.5f * x * (1.0f + erff(x * 0.70710678118654752f));
}

// ---------------- GEMM: C[e] = A[e] @ B[e] + bias[e], tf32 mma.sync ----------------
// CTA tile 128(M) x 256(N) x 8(K). 256 threads = 8 warps in 2(M) x 4(N) grid,
// warp tile 64x64 via m16n8k8: 4 m-frags x 8 n-frags.
#define BM 128
#define BN 256
#define BK 8
#define BKP 12   // As[m][k] pad: banks (12g+tg)%32 all distinct -> conflict-free frag loads
#define BNP 264  // Bs[k][n] pad: banks (8*tg+g)%32 all distinct -> conflict-free frag loads

template <bool FIRST>
__global__ void __launch_bounds__(256, 1) gemm_tf32(
    const float* __restrict__ Ain,   // FIRST: x [NTOK, IN_DIM]; else ignored (reads g_h)
    const float* __restrict__ Bmat,  // [E][K][N] row-major
    const float* __restrict__ bias)  // [E][N]
{
    constexpr int N = FIRST ? HID_DIM : OUT_DIM;
    constexpr int K = FIRST ? IN_DIM : HID_DIM;
    constexpr int NKT = K / BK;

    __shared__ float As[2][BM][BKP];
    __shared__ float Bs[2][BK][BNP];

    const int e  = blockIdx.z;
    const int m0 = blockIdx.y * BM;
    const int n0 = blockIdx.x * BN;

    const float* Ae = FIRST ? Ain : (g_h + (size_t)e * NTOK * K);
    const float* Be = Bmat + (size_t)e * K * N;
    float* Ce = (FIRST ? g_h : g_y) + (size_t)e * NTOK * N;

    const int tid  = threadIdx.x;
    const int lane = tid & 31;
    const int wid  = tid >> 5;
    const int g    = lane >> 2;   // 0..7
    const int tg   = lane & 3;    // 0..3
    const int wm = (wid >> 2) * 64;  // warp row offset within CTA tile
    const int wn = (wid & 3) * 64;   // warp col offset within CTA tile

    // A tile loader: 128 rows x 8 k, one float4 per thread
    const int a_row = tid >> 1;          // 0..127
    const int a_c4  = (tid & 1) << 2;    // 0 or 4
    // B tile loader: 8 k-rows x 256 n, two float4 per thread (rows r and r+4)
    const int b_row = tid >> 6;          // 0..3
    const int b_c   = (tid & 63) << 2;   // 0..252

    float acc[4][8][4];
#pragma unroll
    for (int i = 0; i < 4; i++)
#pragma unroll
        for (int j = 0; j < 8; j++)
#pragma unroll
            for (int r = 0; r < 4; r++) acc[i][j][r] = 0.0f;

    const float* aPtr  = Ae + (size_t)(m0 + a_row) * K + a_c4;
    const float* bPtr0 = Be + (size_t)b_row * N + n0 + b_c;
    const float* bPtr1 = Be + (size_t)(b_row + 4) * N + n0 + b_c;

    float4 aR  = *(const float4*)aPtr;
    float4 bR0 = *(const float4*)bPtr0;
    float4 bR1 = *(const float4*)bPtr1;

    // store tile 0 (convert to tf32 with round-to-nearest)
    {
        float4 t;
        t.x = __uint_as_float(f2tf(aR.x));  t.y = __uint_as_float(f2tf(aR.y));
        t.z = __uint_as_float(f2tf(aR.z));  t.w = __uint_as_float(f2tf(aR.w));
        *(float4*)&As[0][a_row][a_c4] = t;
        t.x = __uint_as_float(f2tf(bR0.x)); t.y = __uint_as_float(f2tf(bR0.y));
        t.z = __uint_as_float(f2tf(bR0.z)); t.w = __uint_as_float(f2tf(bR0.w));
        *(float4*)&Bs[0][b_row][b_c] = t;
        t.x = __uint_as_float(f2tf(bR1.x)); t.y = __uint_as_float(f2tf(bR1.y));
        t.z = __uint_as_float(f2tf(bR1.z)); t.w = __uint_as_float(f2tf(bR1.w));
        *(float4*)&Bs[0][b_row + 4][b_c] = t;
    }
    __syncthreads();

    for (int kt = 0; kt < NKT; kt++) {
        const int cur = kt & 1;
        if (kt + 1 < NKT) {
            const size_t koff = (size_t)(kt + 1) * BK;
            aR  = *(const float4*)(aPtr + koff);
            bR0 = *(const float4*)(bPtr0 + koff * N);
            bR1 = *(const float4*)(bPtr1 + koff * N);
        }

        unsigned af[4][4], bf[8][2];
#pragma unroll
        for (int i = 0; i < 4; i++) {
            af[i][0] = __float_as_uint(As[cur][wm + i * 16 + g][tg]);
            af[i][1] = __float_as_uint(As[cur][wm + i * 16 + g + 8][tg]);
            af[i][2] = __float_as_uint(As[cur][wm + i * 16 + g][tg + 4]);
            af[i][3] = __float_as_uint(As[cur][wm + i * 16 + g + 8][tg + 4]);
        }
#pragma unroll
        for (int j = 0; j < 8; j++) {
            bf[j][0] = __float_as_uint(Bs[cur][tg][wn + j * 8 + g]);
            bf[j][1] = __float_as_uint(Bs[cur][tg + 4][wn + j * 8 + g]);
        }
#pragma unroll
        for (int i = 0; i < 4; i++)
#pragma unroll
            for (int j = 0; j < 8; j++)
                asm volatile(
                    "mma.sync.aligned.m16n8k8.row.col.f32.tf32.tf32.f32 "
                    "{%0,%1,%2,%3}, {%4,%5,%6,%7}, {%8,%9}, {%0,%1,%2,%3};"
                    : "+f"(acc[i][j][0]), "+f"(acc[i][j][1]),
                      "+f"(acc[i][j][2]), "+f"(acc[i][j][3])
                    : "r"(af[i][0]), "r"(af[i][1]), "r"(af[i][2]), "r"(af[i][3]),
                      "r"(bf[j][0]), "r"(bf[j][1]));

        if (kt + 1 < NKT) {
            const int nxt = cur ^ 1;
            float4 t;
            t.x = __uint_as_float(f2tf(aR.x));  t.y = __uint_as_float(f2tf(aR.y));
            t.z = __uint_as_float(f2tf(aR.z));  t.w = __uint_as_float(f2tf(aR.w));
            *(float4*)&As[nxt][a_row][a_c4] = t;
            t.x = __uint_as_float(f2tf(bR0.x)); t.y = __uint_as_float(f2tf(bR0.y));
            t.z = __uint_as_float(f2tf(bR0.z)); t.w = __uint_as_float(f2tf(bR0.w));
            *(float4*)&Bs[nxt][b_row][b_c] = t;
            t.x = __uint_as_float(f2tf(bR1.x)); t.y = __uint_as_float(f2tf(bR1.y));
            t.z = __uint_as_float(f2tf(bR1.z)); t.w = __uint_as_float(f2tf(bR1.w));
            *(float4*)&Bs[nxt][b_row + 4][b_c] = t;
        }
        __syncthreads();
    }

    // Epilogue: add bias, store fp32
#pragma unroll
    for (int i = 0; i < 4; i++) {
        const int row = m0 + wm + i * 16 + g;
#pragma unroll
        for (int j = 0; j < 8; j++) {
            const int col = n0 + wn + j * 8 + tg * 2;
            const float bv0 = bias[(size_t)e * N + col];
            const float bv1 = bias[(size_t)e * N + col + 1];
            float2 v;
            v.x = acc[i][j][0] + bv0;
            v.y = acc[i][j][1] + bv1;
            *(float2*)(Ce + (size_t)row * N + col) = v;
            v.x = acc[i][j][2] + bv0;
            v.y = acc[i][j][3] + bv1;
            *(float2*)(Ce + (size_t)(row + 8) * N + col) = v;
        }
    }
}

// ---------------- LayerNorm + GELU in place on g_h (rows of HID_DIM) ----------------
__global__ void __launch_bounds__(256) ln_gelu_kernel(
    const float* __restrict__ gamma,  // [E][HID]
    const float* __restrict__ beta)   // [E][HID]
{
    __shared__ float red[16];
    const size_t row = blockIdx.x;        // 0 .. NE*NTOK-1, layout [E][NTOK]
    const int e = blockIdx.x >> 13;       // / NTOK (8192 = 2^13)
    float* p = g_h + row * (size_t)HID_DIM;
    const float* gm = gamma + (size_t)e * HID_DIM;
    const float* bt = beta + (size_t)e * HID_DIM;
    const int tid = threadIdx.x;

    float s = 0.f, s2 = 0.f;
#pragma unroll
    for (int i = tid * 4; i < HID_DIM; i += 1024) {
        float4 v = *(const float4*)(p + i);
        s  += v.x + v.y + v.z + v.w;
        s2 += v.x * v.x + v.y * v.y + v.z * v.z + v.w * v.w;
    }
#pragma unroll
    for (int o = 16; o > 0; o >>= 1) {
        s  += __shfl_xor_sync(0xffffffffu, s, o);
        s2 += __shfl_xor_sync(0xffffffffu, s2, o);
    }
    const int wi = tid >> 5, ln = tid & 31;
    if (ln == 0) { red[wi] = s; red[8 + wi] = s2; }
    __syncthreads();
    if (tid == 0) {
        float ts = 0.f, t2 = 0.f;
        for (int k = 0; k < 8; k++) { ts += red[k]; t2 += red[8 + k]; }
        red[0] = ts; red[8] = t2;
    }
    __syncthreads();
    const float invL = 1.0f / (float)HID_DIM;
    const float mean = red[0] * invL;
    const float inv = rsqrtf(red[8] * invL - mean * mean + 1e-5f);
#pragma unroll
    for (int i = tid * 4; i < HID_DIM; i += 1024) {
        float4 v = *(const float4*)(p + i);
        float4 gv = *(const float4*)(gm + i);
        float4 bv = *(const float4*)(bt + i);
        v.x = geluf((v.x - mean) * inv * gv.x + bv.x);
        v.y = geluf((v.y - mean) * inv * gv.y + bv.y);
        v.z = geluf((v.z - mean) * inv * gv.z + bv.z);
        v.w = geluf((v.w - mean) * inv * gv.w + bv.w);
        *(float4*)(p + i) = v;
    }
}

// -------- Final: LN(OUT) + GELU per (e,b), weighted sum over e, write d_out --------
__global__ void __launch_bounds__(256) final_kernel(
    const float* __restrict__ weights,  // [B][E]
    const float* __restrict__ gamma,    // [E][OUT]
    const float* __restrict__ beta,     // [E][OUT]
    float* __restrict__ out)            // [B][OUT]
{
    __shared__ float red[16];
    const int b = blockIdx.x;
    const int tid = threadIdx.x;
    const int wi = tid >> 5, ln = tid & 31;

    float accv[4] = {0.f, 0.f, 0.f, 0.f};
#pragma unroll 1
    for (int e = 0; e < NE; e++) {
        const float* p = g_y + ((size_t)e * NTOK + b) * OUT_DIM;
        float vals[4];
        float s = 0.f, s2 = 0.f;
#pragma unroll
        for (int r = 0; r < 4; r++) {
            float v = p[tid + r * 256];
            vals[r] = v;
            s += v; s2 += v * v;
        }
#pragma unroll
        for (int o = 16; o > 0; o >>= 1) {
            s  += __shfl_xor_sync(0xffffffffu, s, o);
            s2 += __shfl_xor_sync(0xffffffffu, s2, o);
        }
        if (ln == 0) { red[wi] = s; red[8 + wi] = s2; }
        __syncthreads();
        if (tid == 0) {
            float ts = 0.f, t2 = 0.f;
            for (int k = 0; k < 8; k++) { ts += red[k]; t2 += red[8 + k]; }
            red[0] = ts; red[8] = t2;
        }
        __syncthreads();
        const float invL = 1.0f / (float)OUT_DIM;
        const float mean = red[0] * invL;
        const float inv = rsqrtf(red[8] * invL - mean * mean + 1e-5f);
        const float w = weights[(size_t)b * NE + e];
#pragma unroll
        for (int r = 0; r < 4; r++) {
            const int i = tid + r * 256;
            const float v = (vals[r] - mean) * inv * gamma[(size_t)e * OUT_DIM + i]
                          + beta[(size_t)e * OUT_DIM + i];
            accv[r] += w * geluf(v);
        }
        __syncthreads();  // protect red[] before next expert's writes
    }
#pragma unroll
    for (int r = 0; r < 4; r++)
        out[(size_t)b * OUT_DIM + tid + r * 256] = accv[r];
}

// ---------------- launch ----------------
extern "C" void kernel_launch(void* const* d_in, const int* in_sizes, int n_in,
                              void* d_out, int out_size) {
    const float* x   = (const float*)d_in[0];
    const float* wts = (const float*)d_in[1];
    const float* W1  = (const float*)d_in[2];
    const float* b1  = (const float*)d_in[3];
    const float* g1  = (const float*)d_in[4];
    const float* be1 = (const float*)d_in[5];
    const float* W2  = (const float*)d_in[6];
    const float* b2  = (const float*)d_in[7];
    const float* g2  = (const float*)d_in[8];
    const float* be2 = (const float*)d_in[9];
    float* out = (float*)d_out;

    // GEMM1: h[e] = x @ W1[e] + b1[e]
    gemm_tf32<true><<<dim3(HID_DIM / BN, NTOK / BM, NE), 256>>>(x, W1, b1);
    // LN + GELU on h (in place)
    ln_gelu_kernel<<<NE * NTOK, 256>>>(g1, be1);
    // GEMM2: y[e] = h[e] @ W2[e] + b2[e]
    gemm_tf32<false><<<dim3(OUT_DIM / BN, NTOK / BM, NE), 256>>>(nullptr, W2, b2);
    // LN + GELU on y, weighted combine over experts
    final_kernel<<<NTOK, 256>>>(wts, g2, be2, out);
}

// round 3
// speedup vs baseline: 1.5912x; 1.5912x over previous
#include <cuda_runtime.h>
#include <cuda_fp16.h>
#include <cstdint>
#include <cstddef>

#define NTOK 8192
#define IN_DIM 1024
#define HID_DIM 4096
#define OUT_DIM 1024
#define NE 8

// Scratch
__device__ __half g_xh[(size_t)NTOK * IN_DIM];            // x in fp16
__device__ __half g_w1t[(size_t)NE * HID_DIM * IN_DIM];   // W1^T [E][HID][IN] fp16
__device__ __half g_w2t[(size_t)NE * OUT_DIM * HID_DIM];  // W2^T [E][OUT][HID] fp16
__device__ float  g_h [(size_t)NE * NTOK * HID_DIM];      // GEMM1 out fp32
__device__ __half g_hh[(size_t)NE * NTOK * HID_DIM];      // LN+GELU out fp16
__device__ float  g_y [(size_t)NE * NTOK * OUT_DIM];      // GEMM2 out fp32

// ---------------- helpers ----------------
__device__ __forceinline__ float geluf(float x) {
    return 0.5f * x * (1.0f + erff(x * 0.70710678118654752f));
}
__device__ __forceinline__ uint32_t smem_u32(const void* p) {
    uint32_t a;
    asm("{ .reg .u64 t; cvta.to.shared.u64 t, %1; cvt.u32.u64 %0, t; }" : "=r"(a) : "l"(p));
    return a;
}
__device__ __forceinline__ void cpa16(uint32_t dst, const void* src) {
    asm volatile("cp.async.cg.shared.global [%0], [%1], 16;" :: "r"(dst), "l"(src));
}

#define LDM4(r, addr)                                                            \
    asm volatile("ldmatrix.sync.aligned.m8n8.x4.shared.b16 {%0,%1,%2,%3}, [%4];" \
                 : "=r"((r)[0]), "=r"((r)[1]), "=r"((r)[2]), "=r"((r)[3])        \
                 : "r"(addr))

#define MMA16816(c, a, b0, b1)                                                   \
    asm volatile("mma.sync.aligned.m16n8k16.row.col.f32.f16.f16.f32 "            \
                 "{%0,%1,%2,%3}, {%4,%5,%6,%7}, {%8,%9}, {%0,%1,%2,%3};"         \
                 : "+f"((c)[0]), "+f"((c)[1]), "+f"((c)[2]), "+f"((c)[3])        \
                 : "r"((a)[0]), "r"((a)[1]), "r"((a)[2]), "r"((a)[3]),           \
                   "r"(b0), "r"(b1))

// ---------------- fp16 mma.sync GEMM: C[e] = A @ Bt[e]^T + bias[e] ----------------
// A [rows, K] fp16 row-major; Bt [E][N][K] fp16 K-major; C [E][rows][N] fp32.
#define BM 128
#define BN 256
#define BKH 32                  // halves of K per stage (64 bytes of data per row)
#define NSTAGE 4
#define ROWB 80                 // smem row stride bytes (64 data + 16 pad)
#define A_BYTES (BM * ROWB)     // 10240
#define B_BYTES (BN * ROWB)     // 20480
#define STAGE_BYTES (A_BYTES + B_BYTES)
#define SMEM_GEMM (NSTAGE * STAGE_BYTES)   // 122880

template <bool FIRST>
__global__ void __launch_bounds__(256, 1) gemm_h(
    const __half* __restrict__ A, const __half* __restrict__ Bt,
    const float* __restrict__ bias, float* __restrict__ C) {
    constexpr int K = FIRST ? IN_DIM : HID_DIM;
    constexpr int N = FIRST ? HID_DIM : OUT_DIM;
    constexpr int NKT = K / BKH;

    extern __shared__ char smem[];
    const uint32_t sb = smem_u32(smem);

    const int tid = threadIdx.x, lane = tid & 31, wid = tid >> 5;
    const int e = blockIdx.z, m0 = blockIdx.x * BM, n0 = blockIdx.y * BN;

    const __half* Ae = A + (FIRST ? (size_t)0 : (size_t)e * NTOK * K) + (size_t)m0 * K;
    const __half* Be = Bt + (size_t)e * (size_t)N * K + (size_t)n0 * K;
    float* Ce = C + (size_t)e * NTOK * N;

    // loaders: A — thread covers row tid>>1, two 16B chunks; B — row tid, four 16B chunks
    const int ar = tid >> 1, ac = (tid & 1) * 2;
    const __half* aG = Ae + (size_t)ar * K + ac * 8;
    const uint32_t aS = (uint32_t)(ar * ROWB + ac * 16);
    const __half* bG = Be + (size_t)tid * K;
    const uint32_t bS = (uint32_t)(tid * ROWB);

#define LOADST(c, s) do {                                                   \
        uint32_t _b = sb + (uint32_t)(s) * STAGE_BYTES;                     \
        const __half* _ag = aG + (size_t)(c) * BKH;                         \
        const __half* _bg = bG + (size_t)(c) * BKH;                         \
        cpa16(_b + aS, _ag); cpa16(_b + aS + 16, _ag + 8);                  \
        uint32_t _bb = _b + A_BYTES + bS;                                   \
        cpa16(_bb,      _bg);      cpa16(_bb + 16, _bg + 8);                \
        cpa16(_bb + 32, _bg + 16); cpa16(_bb + 48, _bg + 24);               \
    } while (0)

    // warp tile 64x64: warps 2(M) x 4(N)
    const int wm = (wid >> 2) * 64, wn = (wid & 3) * 64;
    const uint32_t lrow = (uint32_t)(lane & 15);
    const uint32_t lhalf = (uint32_t)((lane >> 4) * 16);
    const uint32_t aLd = (uint32_t)((wm + lrow) * ROWB) + lhalf;
    const uint32_t bLd = A_BYTES + (uint32_t)((wn + lrow) * ROWB) + lhalf;

    float acc[4][8][4];
#pragma unroll
    for (int i = 0; i < 4; i++)
#pragma unroll
        for (int j = 0; j < 8; j++)
#pragma unroll
            for (int r = 0; r < 4; r++) acc[i][j][r] = 0.0f;

    // prologue
#pragma unroll
    for (int c = 0; c < NSTAGE - 1; c++) {
        LOADST(c, c);
        asm volatile("cp.async.commit_group;" ::: "memory");
    }

    for (int kt = 0; kt < NKT; kt++) {
        if (kt + NSTAGE - 1 < NKT) LOADST(kt + NSTAGE - 1, (kt + NSTAGE - 1) & (NSTAGE - 1));
        asm volatile("cp.async.commit_group;" ::: "memory");
        asm volatile("cp.async.wait_group %0;" :: "n"(NSTAGE - 1) : "memory");
        __syncthreads();

        const uint32_t base = sb + (uint32_t)(kt & (NSTAGE - 1)) * STAGE_BYTES;
#pragma unroll
        for (int ks = 0; ks < 2; ks++) {
            const uint32_t koff = (uint32_t)(ks * 32);
            uint32_t af[4][4], br[4][4];
#pragma unroll
            for (int i = 0; i < 4; i++) LDM4(af[i], base + aLd + i * (16 * ROWB) + koff);
#pragma unroll
            for (int t = 0; t < 4; t++) LDM4(br[t], base + bLd + t * (16 * ROWB) + koff);
#pragma unroll
            for (int i = 0; i < 4; i++)
#pragma unroll
                for (int j = 0; j < 8; j++) {
                    const int t = j >> 1;
                    const uint32_t b0 = (j & 1) ? br[t][1] : br[t][0];
                    const uint32_t b1 = (j & 1) ? br[t][3] : br[t][2];
                    MMA16816(acc[i][j], af[i], b0, b1);
                }
        }
        __syncthreads();
    }

    // epilogue: bias add, fp32 store
    const int g = lane >> 2, tg = lane & 3;
#pragma unroll
    for (int i = 0; i < 4; i++) {
        const int row = m0 + wm + i * 16 + g;
#pragma unroll
        for (int j = 0; j < 8; j++) {
            const int col = n0 + wn + j * 8 + tg * 2;
            const float bv0 = bias[(size_t)e * N + col];
            const float bv1 = bias[(size_t)e * N + col + 1];
            float2 v;
            v.x = acc[i][j][0] + bv0;
            v.y = acc[i][j][1] + bv1;
            *(float2*)(Ce + (size_t)row * N + col) = v;
            v.x = acc[i][j][2] + bv0;
            v.y = acc[i][j][3] + bv1;
            *(float2*)(Ce + (size_t)(row + 8) * N + col) = v;
        }
    }
#undef LOADST
}

// ---------------- weight transpose + fp16 convert: [K,N] -> [N,K] ----------------
template <bool W1SEL>
__global__ void transpose_h(const float* __restrict__ in, int K, int N) {
    __shared__ float t[32][33];
    __half* out = W1SEL ? g_w1t : g_w2t;
    const int e = blockIdx.z;
    const float* ip = in + (size_t)e * K * N;
    __half* op = out + (size_t)e * K * N;
    const int n0 = blockIdx.x * 32, k0 = blockIdx.y * 32;
#pragma unroll
    for (int r = threadIdx.y; r < 32; r += 8)
        t[r][threadIdx.x] = ip[(size_t)(k0 + r) * N + n0 + threadIdx.x];
    __syncthreads();
#pragma unroll
    for (int r = threadIdx.y; r < 32; r += 8)
        op[(size_t)(n0 + r) * K + k0 + threadIdx.x] = __float2half_rn(t[threadIdx.x][r]);
}

// x -> g_xh fp16
__global__ void copy_h(const float* __restrict__ in) {
    const size_t i = ((size_t)blockIdx.x * 256 + threadIdx.x) * 4;
    float4 v = *(const float4*)(in + i);
    __half2* o = (__half2*)(g_xh + i);
    o[0] = __floats2half2_rn(v.x, v.y);
    o[1] = __floats2half2_rn(v.z, v.w);
}

// ---------------- LayerNorm + GELU: g_h (fp32) -> g_hh (fp16) ----------------
__global__ void __launch_bounds__(256) ln_gelu_kernel(
    const float* __restrict__ gamma, const float* __restrict__ beta) {
    __shared__ float red[16];
    const size_t row = blockIdx.x;
    const int e = blockIdx.x >> 13;
    const float* p = g_h + row * (size_t)HID_DIM;
    __half* ph = g_hh + row * (size_t)HID_DIM;
    const float* gm = gamma + (size_t)e * HID_DIM;
    const float* bt = beta + (size_t)e * HID_DIM;
    const int tid = threadIdx.x;

    float s = 0.f, s2 = 0.f;
#pragma unroll
    for (int i = tid * 4; i < HID_DIM; i += 1024) {
        float4 v = *(const float4*)(p + i);
        s  += v.x + v.y + v.z + v.w;
        s2 += v.x * v.x + v.y * v.y + v.z * v.z + v.w * v.w;
    }
#pragma unroll
    for (int o = 16; o > 0; o >>= 1) {
        s  += __shfl_xor_sync(0xffffffffu, s, o);
        s2 += __shfl_xor_sync(0xffffffffu, s2, o);
    }
    const int wi = tid >> 5, ln = tid & 31;
    if (ln == 0) { red[wi] = s; red[8 + wi] = s2; }
    __syncthreads();
    if (tid == 0) {
        float ts = 0.f, t2 = 0.f;
        for (int k = 0; k < 8; k++) { ts += red[k]; t2 += red[8 + k]; }
        red[0] = ts; red[8] = t2;
    }
    __syncthreads();
    const float invL = 1.0f / (float)HID_DIM;
    const float mean = red[0] * invL;
    const float inv = rsqrtf(red[8] * invL - mean * mean + 1e-5f);
#pragma unroll
    for (int i = tid * 4; i < HID_DIM; i += 1024) {
        float4 v = *(const float4*)(p + i);
        float4 gv = *(const float4*)(gm + i);
        float4 bv = *(const float4*)(bt + i);
        float r0 = geluf((v.x - mean) * inv * gv.x + bv.x);
        float r1 = geluf((v.y - mean) * inv * gv.y + bv.y);
        float r2 = geluf((v.z - mean) * inv * gv.z + bv.z);
        float r3 = geluf((v.w - mean) * inv * gv.w + bv.w);
        __half2* o = (__half2*)(ph + i);
        o[0] = __floats2half2_rn(r0, r1);
        o[1] = __floats2half2_rn(r2, r3);
    }
}

// -------- Final: LN(OUT) + GELU per (e,b), weighted sum over e --------
__global__ void __launch_bounds__(256) final_kernel(
    const float* __restrict__ weights, const float* __restrict__ gamma,
    const float* __restrict__ beta, float* __restrict__ out) {
    __shared__ float red[16];
    const int b = blockIdx.x;
    const int tid = threadIdx.x;
    const int wi = tid >> 5, ln = tid & 31;

    float accv[4] = {0.f, 0.f, 0.f, 0.f};
#pragma unroll 1
    for (int e = 0; e < NE; e++) {
        const float* p = g_y + ((size_t)e * NTOK + b) * OUT_DIM;
        float vals[4];
        float s = 0.f, s2 = 0.f;
#pragma unroll
        for (int r = 0; r < 4; r++) {
            float v = p[tid + r * 256];
            vals[r] = v;
            s += v; s2 += v * v;
        }
#pragma unroll
        for (int o = 16; o > 0; o >>= 1) {
            s  += __shfl_xor_sync(0xffffffffu, s, o);
            s2 += __shfl_xor_sync(0xffffffffu, s2, o);
        }
        if (ln == 0) { red[wi] = s; red[8 + wi] = s2; }
        __syncthreads();
        if (tid == 0) {
            float ts = 0.f, t2 = 0.f;
            for (int k = 0; k < 8; k++) { ts += red[k]; t2 += red[8 + k]; }
            red[0] = ts; red[8] = t2;
        }
        __syncthreads();
        const float invL = 1.0f / (float)OUT_DIM;
        const float mean = red[0] * invL;
        const float inv = rsqrtf(red[8] * invL - mean * mean + 1e-5f);
        const float w = weights[(size_t)b * NE + e];
#pragma unroll
        for (int r = 0; r < 4; r++) {
            const int i = tid + r * 256;
            const float v = (vals[r] - mean) * inv * gamma[(size_t)e * OUT_DIM + i]
                          + beta[(size_t)e * OUT_DIM + i];
            accv[r] += w * geluf(v);
        }
        __syncthreads();
    }
#pragma unroll
    for (int r = 0; r < 4; r++)
        out[(size_t)b * OUT_DIM + tid + r * 256] = accv[r];
}

// ---------------- launch ----------------
extern "C" void kernel_launch(void* const* d_in, const int* in_sizes, int n_in,
                              void* d_out, int out_size) {
    const float* x   = (const float*)d_in[0];
    const float* wts = (const float*)d_in[1];
    const float* W1  = (const float*)d_in[2];
    const float* b1  = (const float*)d_in[3];
    const float* g1  = (const float*)d_in[4];
    const float* be1 = (const float*)d_in[5];
    const float* W2  = (const float*)d_in[6];
    const float* b2  = (const float*)d_in[7];
    const float* g2  = (const float*)d_in[8];
    const float* be2 = (const float*)d_in[9];
    float* out = (float*)d_out;

    cudaFuncSetAttribute(gemm_h<true>,  cudaFuncAttributeMaxDynamicSharedMemorySize, SMEM_GEMM);
    cudaFuncSetAttribute(gemm_h<false>, cudaFuncAttributeMaxDynamicSharedMemorySize, SMEM_GEMM);

    __half* w1t; cudaGetSymbolAddress((void**)&w1t, g_w1t);
    __half* w2t; cudaGetSymbolAddress((void**)&w2t, g_w2t);
    __half* xh;  cudaGetSymbolAddress((void**)&xh,  g_xh);
    __half* hh;  cudaGetSymbolAddress((void**)&hh,  g_hh);
    float* h;    cudaGetSymbolAddress((void**)&h,   g_h);
    float* y;    cudaGetSymbolAddress((void**)&y,   g_y);

    // prep: transpose+convert weights, convert x
    transpose_h<true ><<<dim3(HID_DIM / 32, IN_DIM / 32, NE), dim3(32, 8)>>>(W1, IN_DIM, HID_DIM);
    transpose_h<false><<<dim3(OUT_DIM / 32, HID_DIM / 32, NE), dim3(32, 8)>>>(W2, HID_DIM, OUT_DIM);
    copy_h<<<(NTOK * IN_DIM) / 1024, 256>>>(x);

    // GEMM1: g_h = x @ W1 + b1
    gemm_h<true><<<dim3(NTOK / BM, HID_DIM / BN, NE), 256, SMEM_GEMM>>>(xh, w1t, b1, h);
    // LN + GELU -> fp16
    ln_gelu_kernel<<<NE * NTOK, 256>>>(g1, be1);
    // GEMM2: g_y = hh @ W2 + b2
    gemm_h<false><<<dim3(NTOK / BM, OUT_DIM / BN, NE), 256, SMEM_GEMM>>>(hh, w2t, b2, y);
    // final LN + GELU + weighted combine
    final_kernel<<<NTOK, 256>>>(wts, g2, be2, out);
}

// round 4
// speedup vs baseline: 2.1175x; 1.3308x over previous
#include <cuda_runtime.h>
#include <cuda_fp16.h>
#include <cstdint>
#include <cstddef>

#define NTOK 8192
#define IN_DIM 1024
#define HID_DIM 4096
#define OUT_DIM 1024
#define NE 8

// Scratch
__device__ __half g_xh[(size_t)NTOK * IN_DIM];            // x in fp16
__device__ __half g_w1t[(size_t)NE * HID_DIM * IN_DIM];   // W1^T [E][HID][IN] fp16
__device__ __half g_w2t[(size_t)NE * OUT_DIM * HID_DIM];  // W2^T [E][OUT][HID] fp16
__device__ __half g_hh[(size_t)NE * NTOK * HID_DIM];      // h fp16 (GEMM1 out, LN in-place)
__device__ __half g_yh[(size_t)NE * NTOK * OUT_DIM];      // y fp16 (GEMM2 out)

// ---------------- helpers ----------------
__device__ __forceinline__ float geluf(float x) {
    return 0.5f * x * (1.0f + erff(x * 0.70710678118654752f));
}
__device__ __forceinline__ uint32_t smem_u32(const void* p) {
    uint32_t a;
    asm("{ .reg .u64 t; cvta.to.shared.u64 t, %1; cvt.u32.u64 %0, t; }" : "=r"(a) : "l"(p));
    return a;
}
__device__ __forceinline__ void cpa16(uint32_t dst, const void* src) {
    asm volatile("cp.async.cg.shared.global [%0], [%1], 16;" :: "r"(dst), "l"(src));
}

#define LDM4(r, addr)                                                            \
    asm volatile("ldmatrix.sync.aligned.m8n8.x4.shared.b16 {%0,%1,%2,%3}, [%4];" \
                 : "=r"((r)[0]), "=r"((r)[1]), "=r"((r)[2]), "=r"((r)[3])        \
                 : "r"(addr))

#define MMA16816(c, a, b0, b1)                                                   \
    asm volatile("mma.sync.aligned.m16n8k16.row.col.f32.f16.f16.f32 "            \
                 "{%0,%1,%2,%3}, {%4,%5,%6,%7}, {%8,%9}, {%0,%1,%2,%3};"         \
                 : "+f"((c)[0]), "+f"((c)[1]), "+f"((c)[2]), "+f"((c)[3])        \
                 : "r"((a)[0]), "r"((a)[1]), "r"((a)[2]), "r"((a)[3]),           \
                   "r"(b0), "r"(b1))

// ---------------- fp16 mma.sync GEMM: C[e] = A @ Bt[e]^T + bias[e], fp16 out ----------------
// 512 threads, 16 warps in 4(M) x 4(N), warp tile 32x64.
#define BM 128
#define BN 256
#define BKH 32                  // halves of K per stage
#define NSTAGE 4
#define ROWB 80                 // smem row stride bytes (64 data + 16 pad)
#define A_BYTES (BM * ROWB)     // 10240
#define B_BYTES (BN * ROWB)     // 20480
#define STAGE_BYTES (A_BYTES + B_BYTES)
#define SMEM_GEMM (NSTAGE * STAGE_BYTES)   // 122880

template <bool FIRST>
__global__ void __launch_bounds__(512, 1) gemm_h(
    const __half* __restrict__ A, const __half* __restrict__ Bt,
    const float* __restrict__ bias, __half* __restrict__ C) {
    constexpr int K = FIRST ? IN_DIM : HID_DIM;
    constexpr int N = FIRST ? HID_DIM : OUT_DIM;
    constexpr int NKT = K / BKH;

    extern __shared__ char smem[];
    const uint32_t sb = smem_u32(smem);

    const int tid = threadIdx.x, lane = tid & 31, wid = tid >> 5;
    const int e = blockIdx.z, m0 = blockIdx.x * BM, n0 = blockIdx.y * BN;

    const __half* Ae = A + (FIRST ? (size_t)0 : (size_t)e * NTOK * K) + (size_t)m0 * K;
    const __half* Be = Bt + (size_t)e * (size_t)N * K + (size_t)n0 * K;
    __half* Ce = C + (size_t)e * NTOK * N;

    // loaders (512 threads): A 128x64B = 512 x 16B (1/thread); B 256x64B = 1024 (2/thread)
    const int ar = tid >> 2, ac = tid & 3;
    const __half* aG = Ae + (size_t)ar * K + ac * 8;
    const uint32_t aS = (uint32_t)(ar * ROWB + ac * 16);
    const int brw = tid >> 1, bc = (tid & 1) * 2;
    const __half* bG = Be + (size_t)brw * K + bc * 8;
    const uint32_t bS = (uint32_t)(brw * ROWB + bc * 16);

#define LOADST(c, s) do {                                                   \
        uint32_t _b = sb + (uint32_t)(s) * STAGE_BYTES;                     \
        const __half* _ag = aG + (size_t)(c) * BKH;                         \
        const __half* _bg = bG + (size_t)(c) * BKH;                         \
        cpa16(_b + aS, _ag);                                                \
        uint32_t _bb = _b + A_BYTES + bS;                                   \
        cpa16(_bb, _bg); cpa16(_bb + 16, _bg + 8);                          \
    } while (0)

    // warp tile 32(M) x 64(N): warps 4(M) x 4(N)
    const int wm = (wid >> 2) * 32, wn = (wid & 3) * 64;
    const uint32_t lrow = (uint32_t)(lane & 15);
    const uint32_t lhalf = (uint32_t)((lane >> 4) * 16);
    const uint32_t aLd = (uint32_t)((wm + lrow) * ROWB) + lhalf;
    const uint32_t bLd = A_BYTES + (uint32_t)((wn + lrow) * ROWB) + lhalf;

    float acc[2][8][4];
#pragma unroll
    for (int i = 0; i < 2; i++)
#pragma unroll
        for (int j = 0; j < 8; j++)
#pragma unroll
            for (int r = 0; r < 4; r++) acc[i][j][r] = 0.0f;

    // prologue: 3 stages in flight
#pragma unroll
    for (int c = 0; c < NSTAGE - 1; c++) {
        LOADST(c, c);
        asm volatile("cp.async.commit_group;" ::: "memory");
    }

    for (int kt = 0; kt < NKT; kt++) {
        asm volatile("cp.async.wait_group 2;" ::: "memory");
        __syncthreads();
        if (kt + NSTAGE - 1 < NKT) LOADST(kt + NSTAGE - 1, (kt + NSTAGE - 1) & (NSTAGE - 1));
        asm volatile("cp.async.commit_group;" ::: "memory");

        const uint32_t base = sb + (uint32_t)(kt & (NSTAGE - 1)) * STAGE_BYTES;
#pragma unroll
        for (int ks = 0; ks < 2; ks++) {
            const uint32_t koff = (uint32_t)(ks * 32);
            uint32_t af[2][4], br[4][4];
#pragma unroll
            for (int i = 0; i < 2; i++) LDM4(af[i], base + aLd + i * (16 * ROWB) + koff);
#pragma unroll
            for (int t = 0; t < 4; t++) LDM4(br[t], base + bLd + t * (16 * ROWB) + koff);
#pragma unroll
            for (int i = 0; i < 2; i++)
#pragma unroll
                for (int j = 0; j < 8; j++) {
                    const int t = j >> 1;
                    const uint32_t b0 = (j & 1) ? br[t][1] : br[t][0];
                    const uint32_t b1 = (j & 1) ? br[t][3] : br[t][2];
                    MMA16816(acc[i][j], af[i], b0, b1);
                }
        }
    }

    // epilogue: bias add, fp16 store
    const int g = lane >> 2, tg = lane & 3;
#pragma unroll
    for (int i = 0; i < 2; i++) {
        const int row = m0 + wm + i * 16 + g;
#pragma unroll
        for (int j = 0; j < 8; j++) {
            const int col = n0 + wn + j * 8 + tg * 2;
            const float bv0 = bias[(size_t)e * N + col];
            const float bv1 = bias[(size_t)e * N + col + 1];
            *(__half2*)(Ce + (size_t)row * N + col) =
                __floats2half2_rn(acc[i][j][0] + bv0, acc[i][j][1] + bv1);
            *(__half2*)(Ce + (size_t)(row + 8) * N + col) =
                __floats2half2_rn(acc[i][j][2] + bv0, acc[i][j][3] + bv1);
        }
    }
#undef LOADST
}

// ---------------- weight transpose + fp16 convert: [K,N] -> [N,K] ----------------
template <bool W1SEL>
__global__ void transpose_h(const float* __restrict__ in, int K, int N) {
    __shared__ float t[32][33];
    __half* out = W1SEL ? g_w1t : g_w2t;
    const int e = blockIdx.z;
    const float* ip = in + (size_t)e * K * N;
    __half* op = out + (size_t)e * K * N;
    const int n0 = blockIdx.x * 32, k0 = blockIdx.y * 32;
#pragma unroll
    for (int r = threadIdx.y; r < 32; r += 8)
        t[r][threadIdx.x] = ip[(size_t)(k0 + r) * N + n0 + threadIdx.x];
    __syncthreads();
#pragma unroll
    for (int r = threadIdx.y; r < 32; r += 8)
        op[(size_t)(n0 + r) * K + k0 + threadIdx.x] = __float2half_rn(t[threadIdx.x][r]);
}

// x -> g_xh fp16
__global__ void copy_h(const float* __restrict__ in) {
    const size_t i = ((size_t)blockIdx.x * 256 + threadIdx.x) * 4;
    float4 v = *(const float4*)(in + i);
    __half2* o = (__half2*)(g_xh + i);
    o[0] = __floats2half2_rn(v.x, v.y);
    o[1] = __floats2half2_rn(v.z, v.w);
}

// ---------------- LayerNorm + GELU in place on g_hh (fp16 rows of HID_DIM) ----------------
__global__ void __launch_bounds__(256) ln_gelu_kernel(
    const float* __restrict__ gamma, const float* __restrict__ beta) {
    __shared__ float red[16];
    const size_t row = blockIdx.x;
    const int e = blockIdx.x >> 13;
    __half* p = g_hh + row * (size_t)HID_DIM;
    const float* gm = gamma + (size_t)e * HID_DIM;
    const float* bt = beta + (size_t)e * HID_DIM;
    const int tid = threadIdx.x;

    float vals[16];
    float s = 0.f, s2 = 0.f;
#pragma unroll
    for (int r = 0; r < 4; r++) {
        const int i = tid * 4 + r * 1024;
        __half2 h0 = *(const __half2*)(p + i);
        __half2 h1 = *(const __half2*)(p + i + 2);
        float2 f0 = __half22float2(h0), f1 = __half22float2(h1);
        vals[r * 4 + 0] = f0.x; vals[r * 4 + 1] = f0.y;
        vals[r * 4 + 2] = f1.x; vals[r * 4 + 3] = f1.y;
        s  += f0.x + f0.y + f1.x + f1.y;
        s2 += f0.x * f0.x + f0.y * f0.y + f1.x * f1.x + f1.y * f1.y;
    }
#pragma unroll
    for (int o = 16; o > 0; o >>= 1) {
        s  += __shfl_xor_sync(0xffffffffu, s, o);
        s2 += __shfl_xor_sync(0xffffffffu, s2, o);
    }
    const int wi = tid >> 5, ln = tid & 31;
    if (ln == 0) { red[wi] = s; red[8 + wi] = s2; }
    __syncthreads();
    if (tid == 0) {
        float ts = 0.f, t2 = 0.f;
        for (int k = 0; k < 8; k++) { ts += red[k]; t2 += red[8 + k]; }
        red[0] = ts; red[8] = t2;
    }
    __syncthreads();
    const float invL = 1.0f / (float)HID_DIM;
    const float mean = red[0] * invL;
    const float inv = rsqrtf(red[8] * invL - mean * mean + 1e-5f);
#pragma unroll
    for (int r = 0; r < 4; r++) {
        const int i = tid * 4 + r * 1024;
        float4 gv = *(const float4*)(gm + i);
        float4 bv = *(const float4*)(bt + i);
        float r0 = geluf((vals[r * 4 + 0] - mean) * inv * gv.x + bv.x);
        float r1 = geluf((vals[r * 4 + 1] - mean) * inv * gv.y + bv.y);
        float r2 = geluf((vals[r * 4 + 2] - mean) * inv * gv.z + bv.z);
        float r3 = geluf((vals[r * 4 + 3] - mean) * inv * gv.w + bv.w);
        *(__half2*)(p + i)     = __floats2half2_rn(r0, r1);
        *(__half2*)(p + i + 2) = __floats2half2_rn(r2, r3);
    }
}

// -------- Final: LN(OUT) + GELU per (e,b), weighted sum over e --------
__global__ void __launch_bounds__(256) final_kernel(
    const float* __restrict__ weights, const float* __restrict__ gamma,
    const float* __restrict__ beta, float* __restrict__ out) {
    __shared__ float red[16];
    const int b = blockIdx.x;
    const int tid = threadIdx.x;
    const int wi = tid >> 5, ln = tid & 31;

    float accv[4] = {0.f, 0.f, 0.f, 0.f};
#pragma unroll 1
    for (int e = 0; e < NE; e++) {
        const __half* p = g_yh + ((size_t)e * NTOK + b) * OUT_DIM;
        float vals[4];
        float s = 0.f, s2 = 0.f;
#pragma unroll
        for (int r = 0; r < 4; r++) {
            float v = __half2float(p[tid + r * 256]);
            vals[r] = v;
            s += v; s2 += v * v;
        }
#pragma unroll
        for (int o = 16; o > 0; o >>= 1) {
            s  += __shfl_xor_sync(0xffffffffu, s, o);
            s2 += __shfl_xor_sync(0xffffffffu, s2, o);
        }
        if (ln == 0) { red[wi] = s; red[8 + wi] = s2; }
        __syncthreads();
        if (tid == 0) {
            float ts = 0.f, t2 = 0.f;
            for (int k = 0; k < 8; k++) { ts += red[k]; t2 += red[8 + k]; }
            red[0] = ts; red[8] = t2;
        }
        __syncthreads();
        const float invL = 1.0f / (float)OUT_DIM;
        const float mean = red[0] * invL;
        const float inv = rsqrtf(red[8] * invL - mean * mean + 1e-5f);
        const float w = weights[(size_t)b * NE + e];
#pragma unroll
        for (int r = 0; r < 4; r++) {
            const int i = tid + r * 256;
            const float v = (vals[r] - mean) * inv * gamma[(size_t)e * OUT_DIM + i]
                          + beta[(size_t)e * OUT_DIM + i];
            accv[r] += w * geluf(v);
        }
        __syncthreads();
    }
#pragma unroll
    for (int r = 0; r < 4; r++)
        out[(size_t)b * OUT_DIM + tid + r * 256] = accv[r];
}

// ---------------- launch ----------------
extern "C" void kernel_launch(void* const* d_in, const int* in_sizes, int n_in,
                              void* d_out, int out_size) {
    const float* x   = (const float*)d_in[0];
    const float* wts = (const float*)d_in[1];
    const float* W1  = (const float*)d_in[2];
    const float* b1  = (const float*)d_in[3];
    const float* g1  = (const float*)d_in[4];
    const float* be1 = (const float*)d_in[5];
    const float* W2  = (const float*)d_in[6];
    const float* b2  = (const float*)d_in[7];
    const float* g2  = (const float*)d_in[8];
    const float* be2 = (const float*)d_in[9];
    float* out = (float*)d_out;

    cudaFuncSetAttribute(gemm_h<true>,  cudaFuncAttributeMaxDynamicSharedMemorySize, SMEM_GEMM);
    cudaFuncSetAttribute(gemm_h<false>, cudaFuncAttributeMaxDynamicSharedMemorySize, SMEM_GEMM);

    __half* w1t; cudaGetSymbolAddress((void**)&w1t, g_w1t);
    __half* w2t; cudaGetSymbolAddress((void**)&w2t, g_w2t);
    __half* xh;  cudaGetSymbolAddress((void**)&xh,  g_xh);
    __half* hh;  cudaGetSymbolAddress((void**)&hh,  g_hh);
    __half* yh;  cudaGetSymbolAddress((void**)&yh,  g_yh);

    // prep: transpose+convert weights, convert x
    transpose_h<true ><<<dim3(HID_DIM / 32, IN_DIM / 32, NE), dim3(32, 8)>>>(W1, IN_DIM, HID_DIM);
    transpose_h<false><<<dim3(OUT_DIM / 32, HID_DIM / 32, NE), dim3(32, 8)>>>(W2, HID_DIM, OUT_DIM);
    copy_h<<<(NTOK * IN_DIM) / 1024, 256>>>(x);

    // GEMM1: g_hh = x @ W1 + b1  (fp16)
    gemm_h<true><<<dim3(NTOK / BM, HID_DIM / BN, NE), 512, SMEM_GEMM>>>(xh, w1t, b1, hh);
    // LN + GELU in place on g_hh
    ln_gelu_kernel<<<NE * NTOK, 256>>>(g1, be1);
    // GEMM2: g_yh = hh @ W2 + b2 (fp16)
    gemm_h<false><<<dim3(NTOK / BM, OUT_DIM / BN, NE), 512, SMEM_GEMM>>>(hh, w2t, b2, yh);
    // final LN + GELU + weighted combine
    final_kernel<<<NTOK, 256>>>(wts, g2, be2, out);
}